// round 3
// baseline (speedup 1.0000x reference)
#include <cuda_runtime.h>
#include <cuda_bf16.h>
#include <math.h>

#define N_NODES 100000
#define E_EDGES 3200000
#define NFEAT 256
#define NHID 128
#define NCLASS 64

// Scratch (allocation-free rule: __device__ globals)
__device__ __align__(256) float g_tmp[(size_t)N_NODES * NHID];
__device__ __align__(256) float g_agg[(size_t)N_NODES * NHID];
__device__ __align__(256) float g_h[(size_t)N_NODES * NHID];
__device__ __align__(256) float g_nsrc[N_NODES];
__device__ __align__(256) float g_ndst[N_NODES];
__device__ __align__(256) int g_degout[N_NODES];
__device__ __align__(256) int g_degin[N_NODES];

// ---------------- utility kernels ----------------

__global__ void zero_deg_k() {
    int i = blockIdx.x * blockDim.x + threadIdx.x;
    if (i < N_NODES) { g_degout[i] = 0; g_degin[i] = 0; }
}

__global__ void zero_f4_k(float4* __restrict__ p, int n4) {
    int stride = gridDim.x * blockDim.x;
    for (int i = blockIdx.x * blockDim.x + threadIdx.x; i < n4; i += stride)
        p[i] = make_float4(0.f, 0.f, 0.f, 0.f);
}

__global__ void degree_k(const int* __restrict__ src,
                         const int* __restrict__ dst) {
    int e = blockIdx.x * blockDim.x + threadIdx.x;
    if (e < E_EDGES) {
        atomicAdd(&g_degout[src[e]], 1);
        atomicAdd(&g_degin[dst[e]], 1);
    }
}

__global__ void norms_k() {
    int i = blockIdx.x * blockDim.x + threadIdx.x;
    if (i < N_NODES) {
        int dov = g_degout[i];
        int div_ = g_degin[i];
        g_nsrc[i] = rsqrtf((float)(dov > 0 ? dov : 1));
        g_ndst[i] = rsqrtf((float)(div_ > 0 ? div_ : 1));
    }
}

// ---------------- GEMM: out[i,j] = (sum_k H[i,k] W[k,j]) * n_src[i] ----------------
// Block: OUT threads (one per output column), TR rows per block.
template <int IN, int OUT>
__global__ void gemm_scale_k(const float* __restrict__ H,
                             const float* __restrict__ W,
                             float* __restrict__ out) {
    const int TR = 8;
    __shared__ float4 Hs[TR * (IN / 4)];

    int row0 = blockIdx.x * TR;
    int tid = threadIdx.x;

    // cooperative load of TR contiguous rows as float4
    const float4* Hg = reinterpret_cast<const float4*>(H + (size_t)row0 * IN);
    for (int i = tid; i < TR * (IN / 4); i += OUT) Hs[i] = Hg[i];
    __syncthreads();

    float acc[TR];
#pragma unroll
    for (int r = 0; r < TR; r++) acc[r] = 0.f;

    for (int k4 = 0; k4 < IN / 4; k4++) {
        float w0 = W[(4 * k4 + 0) * OUT + tid];
        float w1 = W[(4 * k4 + 1) * OUT + tid];
        float w2 = W[(4 * k4 + 2) * OUT + tid];
        float w3 = W[(4 * k4 + 3) * OUT + tid];
#pragma unroll
        for (int r = 0; r < TR; r++) {
            float4 h = Hs[r * (IN / 4) + k4];
            acc[r] += h.x * w0 + h.y * w1 + h.z * w2 + h.w * w3;
        }
    }

#pragma unroll
    for (int r = 0; r < TR; r++) {
        out[(size_t)(row0 + r) * OUT + tid] = acc[r] * g_nsrc[row0 + r];
    }
}

// ---------------- SpMM: agg[dst] += tmp[src] (tmp already scaled by n_src) ----------------

// 128 features: warp per edge, float4 per lane, vector RED
__global__ void spmm128_k(const int* __restrict__ src,
                          const int* __restrict__ dst,
                          const float* __restrict__ tmp,
                          float* __restrict__ agg) {
    long long gtid = (long long)blockIdx.x * blockDim.x + threadIdx.x;
    int e = (int)(gtid >> 5);
    int lane = (int)(gtid & 31);
    if (e >= E_EDGES) return;
    int s = src[e];
    int d = dst[e];
    float4 v = *reinterpret_cast<const float4*>(tmp + (size_t)s * 128 + lane * 4);
    float* p = agg + (size_t)d * 128 + lane * 4;
    asm volatile("red.global.add.v4.f32 [%0], {%1, %2, %3, %4};"
                 :: "l"(p), "f"(v.x), "f"(v.y), "f"(v.z), "f"(v.w)
                 : "memory");
}

// 64 features: warp per edge, float2 per lane
__global__ void spmm64_k(const int* __restrict__ src,
                         const int* __restrict__ dst,
                         const float* __restrict__ tmp,
                         float* __restrict__ agg) {
    long long gtid = (long long)blockIdx.x * blockDim.x + threadIdx.x;
    int e = (int)(gtid >> 5);
    int lane = (int)(gtid & 31);
    if (e >= E_EDGES) return;
    int s = src[e];
    int d = dst[e];
    float2 v = *reinterpret_cast<const float2*>(tmp + (size_t)s * 64 + lane * 2);
    float* p = agg + (size_t)d * 64 + lane * 2;
    asm volatile("red.global.add.v2.f32 [%0], {%1, %2};"
                 :: "l"(p), "f"(v.x), "f"(v.y)
                 : "memory");
}

// ---------------- finalize: h = agg * n_dst + b ----------------
__global__ void finalize128_k(const float* __restrict__ agg,
                              const float* __restrict__ b,
                              float* __restrict__ h) {
    int i = blockIdx.x * blockDim.x + threadIdx.x;
    if (i < N_NODES * NHID) {
        int r = i >> 7;
        int c = i & 127;
        h[i] = agg[i] * g_ndst[r] + b[c];
    }
}

// last layer: h = agg * n_dst + b2, then softmax over 64 classes. Warp per row.
__global__ void finalize_softmax_k(const float* __restrict__ agg,
                                   const float* __restrict__ b,
                                   float* __restrict__ out) {
    long long gtid = (long long)blockIdx.x * blockDim.x + threadIdx.x;
    int row = (int)(gtid >> 5);
    int lane = threadIdx.x & 31;
    if (row >= N_NODES) return;
    float nd = g_ndst[row];
    float2 v = *reinterpret_cast<const float2*>(agg + (size_t)row * 64 + lane * 2);
    float2 bb = *reinterpret_cast<const float2*>(b + lane * 2);
    float a0 = v.x * nd + bb.x;
    float a1 = v.y * nd + bb.y;
    float m = fmaxf(a0, a1);
#pragma unroll
    for (int o = 16; o > 0; o >>= 1) m = fmaxf(m, __shfl_xor_sync(0xffffffffu, m, o));
    float e0 = __expf(a0 - m);
    float e1 = __expf(a1 - m);
    float s = e0 + e1;
#pragma unroll
    for (int o = 16; o > 0; o >>= 1) s += __shfl_xor_sync(0xffffffffu, s, o);
    float inv = 1.f / s;
    reinterpret_cast<float2*>(out + (size_t)row * 64)[lane] = make_float2(e0 * inv, e1 * inv);
}

// ---------------- launch ----------------

extern "C" void kernel_launch(void* const* d_in, const int* in_sizes, int n_in,
                              void* d_out, int out_size) {
    const float* x = (const float*)d_in[0];
    const int* src = (const int*)d_in[1];
    const int* dst = (const int*)d_in[2];
    const float* W0 = (const float*)d_in[3];
    const float* b0 = (const float*)d_in[4];
    const float* W1 = (const float*)d_in[5];
    const float* b1 = (const float*)d_in[6];
    const float* W2 = (const float*)d_in[7];
    const float* b2 = (const float*)d_in[8];
    float* out = (float*)d_out;

    float *tmp, *agg, *h;
    cudaGetSymbolAddress((void**)&tmp, g_tmp);
    cudaGetSymbolAddress((void**)&agg, g_agg);
    cudaGetSymbolAddress((void**)&h, g_h);

    const int TPB = 256;
    const int nodeBlocks = (N_NODES + TPB - 1) / TPB;
    const int edgeBlocks = (E_EDGES + TPB - 1) / TPB;
    const int edgeWarpBlocks = (int)(((size_t)E_EDGES * 32 + TPB - 1) / TPB);
    const int nodeWarpBlocks = (int)(((size_t)N_NODES * 32 + TPB - 1) / TPB);
    const int zeroBlocks = 2048;

    // degrees + norms
    zero_deg_k<<<nodeBlocks, TPB>>>();
    degree_k<<<edgeBlocks, TPB>>>(src, dst);
    norms_k<<<nodeBlocks, TPB>>>();

    // ---- Layer 0: 256 -> 128 ----
    gemm_scale_k<NFEAT, NHID><<<N_NODES / 8, NHID>>>(x, W0, tmp);
    zero_f4_k<<<zeroBlocks, TPB>>>((float4*)agg, N_NODES * NHID / 4);
    spmm128_k<<<edgeWarpBlocks, TPB>>>(src, dst, tmp, agg);
    finalize128_k<<<(N_NODES * NHID + TPB - 1) / TPB, TPB>>>(agg, b0, h);

    // ---- Layer 1: 128 -> 128 ----
    gemm_scale_k<NHID, NHID><<<N_NODES / 8, NHID>>>(h, W1, tmp);
    zero_f4_k<<<zeroBlocks, TPB>>>((float4*)agg, N_NODES * NHID / 4);
    spmm128_k<<<edgeWarpBlocks, TPB>>>(src, dst, tmp, agg);
    finalize128_k<<<(N_NODES * NHID + TPB - 1) / TPB, TPB>>>(agg, b1, h);

    // ---- Layer 2: 128 -> 64, + softmax ----
    gemm_scale_k<NHID, NCLASS><<<N_NODES / 8, NCLASS>>>(h, W2, tmp);
    zero_f4_k<<<zeroBlocks, TPB>>>((float4*)agg, N_NODES * NCLASS / 4);
    spmm64_k<<<edgeWarpBlocks, TPB>>>(src, dst, tmp, agg);
    finalize_softmax_k<<<nodeWarpBlocks, TPB>>>(agg, b2, out);
}

// round 5
// speedup vs baseline: 1.8412x; 1.8412x over previous
#include <cuda_runtime.h>
#include <cuda_bf16.h>
#include <math.h>

#define N_NODES 100000
#define E_EDGES 3200000
#define NFEAT 256
#define NHID 128
#define NCLASS 64

// Scratch (allocation-free rule: __device__ globals)
__device__ __align__(256) float g_tmp[(size_t)N_NODES * NHID];
__device__ __align__(256) float g_h[(size_t)N_NODES * NHID];
__device__ __align__(256) float g_nsrc[N_NODES];
__device__ __align__(256) float g_ndst[N_NODES];
__device__ __align__(256) int g_degout[N_NODES];
__device__ __align__(256) int g_degin[N_NODES];
__device__ __align__(256) int g_rowptr[N_NODES + 1];
__device__ __align__(256) int g_cursor[N_NODES];
__device__ __align__(256) int g_csr[E_EDGES];

// ---------------- degree / norms ----------------

__global__ void zero_deg_k() {
    int i = blockIdx.x * blockDim.x + threadIdx.x;
    if (i < N_NODES) { g_degout[i] = 0; g_degin[i] = 0; }
}

__global__ void degree_k(const int* __restrict__ src,
                         const int* __restrict__ dst) {
    int e = blockIdx.x * blockDim.x + threadIdx.x;
    if (e < E_EDGES) {
        atomicAdd(&g_degout[src[e]], 1);
        atomicAdd(&g_degin[dst[e]], 1);
    }
}

__global__ void norms_k() {
    int i = blockIdx.x * blockDim.x + threadIdx.x;
    if (i < N_NODES) {
        int dov = g_degout[i];
        int div_ = g_degin[i];
        g_nsrc[i] = rsqrtf((float)(dov > 0 ? dov : 1));
        g_ndst[i] = rsqrtf((float)(div_ > 0 ? div_ : 1));
    }
}

// ---------------- exclusive scan of deg_in -> rowptr (+ cursor copy) ----------------
// Single block, 1024 threads, chunked Hillis-Steele.
__global__ void scan_k() {
    __shared__ int s[1024];
    __shared__ int carry;
    int tid = threadIdx.x;
    if (tid == 0) carry = 0;
    __syncthreads();
    for (int base = 0; base < N_NODES; base += 1024) {
        int idx = base + tid;
        int v = (idx < N_NODES) ? g_degin[idx] : 0;
        s[tid] = v;
        __syncthreads();
#pragma unroll
        for (int off = 1; off < 1024; off <<= 1) {
            int t = (tid >= off) ? s[tid - off] : 0;
            __syncthreads();
            s[tid] += t;
            __syncthreads();
        }
        int excl = carry + s[tid] - v;
        if (idx < N_NODES) { g_rowptr[idx] = excl; g_cursor[idx] = excl; }
        __syncthreads();
        if (tid == 1023) carry += s[1023];
        __syncthreads();
    }
    if (tid == 0) g_rowptr[N_NODES] = E_EDGES;
}

__global__ void scatter_k(const int* __restrict__ src,
                          const int* __restrict__ dst) {
    int e = blockIdx.x * blockDim.x + threadIdx.x;
    if (e < E_EDGES) {
        int pos = atomicAdd(&g_cursor[dst[e]], 1);
        g_csr[pos] = src[e];
    }
}

// ---------------- GEMM: out[i,j] = (sum_k H[i,k] W[k,j]) * n_src[i] ----------------
// 128 threads, 32-row x OUT-col tile, each thread R rows x 4 cols.
template <int IN, int OUT>
__global__ void gemm_scale_k(const float* __restrict__ H,
                             const float* __restrict__ W,
                             float* __restrict__ out) {
    constexpr int CG = OUT / 4;     // col groups
    constexpr int RG = 128 / CG;    // row groups
    constexpr int R = 32 / RG;      // rows per thread
    __shared__ float Hs[32 * IN];

    int tid = threadIdx.x;
    int row0 = blockIdx.x * 32;

    // cooperative load of 32 contiguous rows as float4 (coalesced)
    {
        const float4* Hg = reinterpret_cast<const float4*>(H + (size_t)row0 * IN);
        float4* Hs4 = reinterpret_cast<float4*>(Hs);
#pragma unroll
        for (int i = tid; i < 32 * IN / 4; i += 128) Hs4[i] = Hg[i];
    }
    __syncthreads();

    int tx = tid % CG;
    int ty = tid / CG;
    const float* hbase = Hs + (size_t)(ty * R) * IN;

    float acc[R][4];
#pragma unroll
    for (int r = 0; r < R; r++)
#pragma unroll
        for (int c = 0; c < 4; c++) acc[r][c] = 0.f;

    for (int k = 0; k < IN; k += 2) {
        float4 w0 = *reinterpret_cast<const float4*>(W + (size_t)k * OUT + tx * 4);
        float4 w1 = *reinterpret_cast<const float4*>(W + (size_t)(k + 1) * OUT + tx * 4);
#pragma unroll
        for (int r = 0; r < R; r++) {
            float2 hv = *reinterpret_cast<const float2*>(hbase + (size_t)r * IN + k);
            acc[r][0] += hv.x * w0.x + hv.y * w1.x;
            acc[r][1] += hv.x * w0.y + hv.y * w1.y;
            acc[r][2] += hv.x * w0.z + hv.y * w1.z;
            acc[r][3] += hv.x * w0.w + hv.y * w1.w;
        }
    }

#pragma unroll
    for (int r = 0; r < R; r++) {
        int row = row0 + ty * R + r;
        float ns = g_nsrc[row];
        float4 o = make_float4(acc[r][0] * ns, acc[r][1] * ns,
                               acc[r][2] * ns, acc[r][3] * ns);
        *reinterpret_cast<float4*>(out + (size_t)row * OUT + tx * 4) = o;
    }
}

// ---------------- CSR SpMM, fused finalize: h[d] = (sum_src tmp[src]) * n_dst[d] + b ----------------
// warp per dst node, float4 per lane (128 features)
__global__ void spmm_csr128_k(const float* __restrict__ tmp,
                              const float* __restrict__ b,
                              float* __restrict__ h) {
    int w = (blockIdx.x * blockDim.x + threadIdx.x) >> 5;
    int lane = threadIdx.x & 31;
    if (w >= N_NODES) return;
    int beg = g_rowptr[w];
    int end = g_rowptr[w + 1];
    float4 acc = make_float4(0.f, 0.f, 0.f, 0.f);
    int i = beg;
    for (; i + 3 < end; i += 4) {
        int s0 = g_csr[i], s1 = g_csr[i + 1], s2 = g_csr[i + 2], s3 = g_csr[i + 3];
        float4 v0 = *reinterpret_cast<const float4*>(tmp + (size_t)s0 * 128 + lane * 4);
        float4 v1 = *reinterpret_cast<const float4*>(tmp + (size_t)s1 * 128 + lane * 4);
        float4 v2 = *reinterpret_cast<const float4*>(tmp + (size_t)s2 * 128 + lane * 4);
        float4 v3 = *reinterpret_cast<const float4*>(tmp + (size_t)s3 * 128 + lane * 4);
        acc.x += v0.x + v1.x + v2.x + v3.x;
        acc.y += v0.y + v1.y + v2.y + v3.y;
        acc.z += v0.z + v1.z + v2.z + v3.z;
        acc.w += v0.w + v1.w + v2.w + v3.w;
    }
    for (; i < end; i++) {
        int s = g_csr[i];
        float4 v = *reinterpret_cast<const float4*>(tmp + (size_t)s * 128 + lane * 4);
        acc.x += v.x; acc.y += v.y; acc.z += v.z; acc.w += v.w;
    }
    float nd = g_ndst[w];
    float4 bb = *reinterpret_cast<const float4*>(b + lane * 4);
    float4 o = make_float4(acc.x * nd + bb.x, acc.y * nd + bb.y,
                           acc.z * nd + bb.z, acc.w * nd + bb.w);
    *reinterpret_cast<float4*>(h + (size_t)w * 128 + lane * 4) = o;
}

// 64 features, fused finalize + softmax. warp per dst node, float2 per lane.
__global__ void spmm_csr64_softmax_k(const float* __restrict__ tmp,
                                     const float* __restrict__ b,
                                     float* __restrict__ out) {
    int w = (blockIdx.x * blockDim.x + threadIdx.x) >> 5;
    int lane = threadIdx.x & 31;
    if (w >= N_NODES) return;
    int beg = g_rowptr[w];
    int end = g_rowptr[w + 1];
    float2 acc = make_float2(0.f, 0.f);
    int i = beg;
    for (; i + 3 < end; i += 4) {
        int s0 = g_csr[i], s1 = g_csr[i + 1], s2 = g_csr[i + 2], s3 = g_csr[i + 3];
        float2 v0 = *reinterpret_cast<const float2*>(tmp + (size_t)s0 * 64 + lane * 2);
        float2 v1 = *reinterpret_cast<const float2*>(tmp + (size_t)s1 * 64 + lane * 2);
        float2 v2 = *reinterpret_cast<const float2*>(tmp + (size_t)s2 * 64 + lane * 2);
        float2 v3 = *reinterpret_cast<const float2*>(tmp + (size_t)s3 * 64 + lane * 2);
        acc.x += v0.x + v1.x + v2.x + v3.x;
        acc.y += v0.y + v1.y + v2.y + v3.y;
    }
    for (; i < end; i++) {
        int s = g_csr[i];
        float2 v = *reinterpret_cast<const float2*>(tmp + (size_t)s * 64 + lane * 2);
        acc.x += v.x; acc.y += v.y;
    }
    float nd = g_ndst[w];
    float2 bb = *reinterpret_cast<const float2*>(b + lane * 2);
    float a0 = acc.x * nd + bb.x;
    float a1 = acc.y * nd + bb.y;
    float m = fmaxf(a0, a1);
#pragma unroll
    for (int o = 16; o > 0; o >>= 1) m = fmaxf(m, __shfl_xor_sync(0xffffffffu, m, o));
    float e0 = __expf(a0 - m);
    float e1 = __expf(a1 - m);
    float s = e0 + e1;
#pragma unroll
    for (int o = 16; o > 0; o >>= 1) s += __shfl_xor_sync(0xffffffffu, s, o);
    float inv = 1.f / s;
    reinterpret_cast<float2*>(out + (size_t)w * 64)[lane] = make_float2(e0 * inv, e1 * inv);
}

// ---------------- launch ----------------

extern "C" void kernel_launch(void* const* d_in, const int* in_sizes, int n_in,
                              void* d_out, int out_size) {
    const float* x = (const float*)d_in[0];
    const int* src = (const int*)d_in[1];
    const int* dst = (const int*)d_in[2];
    const float* W0 = (const float*)d_in[3];
    const float* b0 = (const float*)d_in[4];
    const float* W1 = (const float*)d_in[5];
    const float* b1 = (const float*)d_in[6];
    const float* W2 = (const float*)d_in[7];
    const float* b2 = (const float*)d_in[8];
    float* out = (float*)d_out;

    float *tmp, *h;
    cudaGetSymbolAddress((void**)&tmp, g_tmp);
    cudaGetSymbolAddress((void**)&h, g_h);

    const int TPB = 256;
    const int nodeBlocks = (N_NODES + TPB - 1) / TPB;
    const int edgeBlocks = (E_EDGES + TPB - 1) / TPB;
    const int nodeWarpBlocks = (int)(((size_t)N_NODES * 32 + TPB - 1) / TPB);

    // degrees, norms, CSR build
    zero_deg_k<<<nodeBlocks, TPB>>>();
    degree_k<<<edgeBlocks, TPB>>>(src, dst);
    norms_k<<<nodeBlocks, TPB>>>();
    scan_k<<<1, 1024>>>();
    scatter_k<<<edgeBlocks, TPB>>>(src, dst);

    // ---- Layer 0: 256 -> 128 ----
    gemm_scale_k<NFEAT, NHID><<<N_NODES / 32, 128>>>(x, W0, tmp);
    spmm_csr128_k<<<nodeWarpBlocks, TPB>>>(tmp, b0, h);

    // ---- Layer 1: 128 -> 128 ----
    gemm_scale_k<NHID, NHID><<<N_NODES / 32, 128>>>(h, W1, tmp);
    spmm_csr128_k<<<nodeWarpBlocks, TPB>>>(tmp, b1, h);

    // ---- Layer 2: 128 -> 64, + softmax ----
    gemm_scale_k<NHID, NCLASS><<<N_NODES / 32, 128>>>(h, W2, tmp);
    spmm_csr64_softmax_k<<<nodeWarpBlocks, TPB>>>(tmp, b2, out);
}

// round 6
// speedup vs baseline: 2.1755x; 1.1816x over previous
#include <cuda_runtime.h>
#include <cuda_bf16.h>
#include <math.h>

#define N_NODES 100000
#define E_EDGES 3200000
#define NFEAT 256
#define NHID 128
#define NCLASS 64

#define SCAN_CHUNK 1024
#define SCAN_NB ((N_NODES + SCAN_CHUNK - 1) / SCAN_CHUNK)   // 98

// Scratch (allocation-free rule: __device__ globals)
__device__ __align__(256) float g_tmp[(size_t)N_NODES * NHID];
__device__ __align__(256) float g_h[(size_t)N_NODES * NHID];
__device__ __align__(256) float g_nsrc[N_NODES];
__device__ __align__(256) float g_ndst[N_NODES];
__device__ __align__(256) int g_degout[N_NODES];
__device__ __align__(256) int g_degin[N_NODES];
__device__ __align__(256) int g_rowptr[N_NODES + 1];
__device__ __align__(256) int g_cursor[N_NODES];
__device__ __align__(256) int g_csr[E_EDGES];
__device__ __align__(256) int g_blocksums[SCAN_NB];

// ---------------- degree / norms ----------------

__global__ void zero_deg_k() {
    int i = blockIdx.x * blockDim.x + threadIdx.x;
    if (i < N_NODES) { g_degout[i] = 0; g_degin[i] = 0; }
}

__global__ void degree_k(const int* __restrict__ src,
                         const int* __restrict__ dst) {
    int e = blockIdx.x * blockDim.x + threadIdx.x;
    if (e < E_EDGES) {
        atomicAdd(&g_degout[src[e]], 1);
        atomicAdd(&g_degin[dst[e]], 1);
    }
}

__global__ void norms_k() {
    int i = blockIdx.x * blockDim.x + threadIdx.x;
    if (i < N_NODES) {
        int dov = g_degout[i];
        int div_ = g_degin[i];
        g_nsrc[i] = rsqrtf((float)(dov > 0 ? dov : 1));
        g_ndst[i] = rsqrtf((float)(div_ > 0 ? div_ : 1));
    }
}

// ---------------- 3-phase exclusive scan of deg_in -> rowptr/cursor ----------------

// Phase 1: per-block (1024-elem chunk) sum
__global__ void blocksum_k() {
    int base = blockIdx.x * SCAN_CHUNK;
    int tid = threadIdx.x;           // 256 threads, 4 elems each
    int s = 0;
#pragma unroll
    for (int j = 0; j < 4; j++) {
        int idx = base + tid * 4 + j;
        if (idx < N_NODES) s += g_degin[idx];
    }
#pragma unroll
    for (int o = 16; o > 0; o >>= 1) s += __shfl_xor_sync(0xffffffffu, s, o);
    __shared__ int ws[8];
    if ((tid & 31) == 0) ws[tid >> 5] = s;
    __syncthreads();
    if (tid == 0) {
        int t = 0;
#pragma unroll
        for (int w = 0; w < 8; w++) t += ws[w];
        g_blocksums[blockIdx.x] = t;
    }
}

// Phase 2: exclusive scan of the 98 block sums (single block, 128 threads)
__global__ void scanblocks_k() {
    __shared__ int s[128];
    int tid = threadIdx.x;
    int v = (tid < SCAN_NB) ? g_blocksums[tid] : 0;
    s[tid] = v;
    __syncthreads();
#pragma unroll
    for (int off = 1; off < 128; off <<= 1) {
        int t = (tid >= off) ? s[tid - off] : 0;
        __syncthreads();
        s[tid] += t;
        __syncthreads();
    }
    if (tid < SCAN_NB) g_blocksums[tid] = s[tid] - v;  // exclusive
}

// Phase 3: local exclusive scan within each chunk + block offset
__global__ void localscan_k() {
    int base = blockIdx.x * SCAN_CHUNK;
    int tid = threadIdx.x;           // 256 threads, 4 consecutive elems each
    int lane = tid & 31;
    int warp = tid >> 5;

    int e0 = base + tid * 4;
    int d0 = (e0 + 0 < N_NODES) ? g_degin[e0 + 0] : 0;
    int d1 = (e0 + 1 < N_NODES) ? g_degin[e0 + 1] : 0;
    int d2 = (e0 + 2 < N_NODES) ? g_degin[e0 + 2] : 0;
    int d3 = (e0 + 3 < N_NODES) ? g_degin[e0 + 3] : 0;
    int tsum = d0 + d1 + d2 + d3;

    // inclusive warp scan of thread sums
    int inc = tsum;
#pragma unroll
    for (int o = 1; o < 32; o <<= 1) {
        int t = __shfl_up_sync(0xffffffffu, inc, o);
        if (lane >= o) inc += t;
    }
    __shared__ int wsum[8];
    if (lane == 31) wsum[warp] = inc;
    __syncthreads();
    __shared__ int woff[8];
    if (tid == 0) {
        int acc = 0;
#pragma unroll
        for (int w = 0; w < 8; w++) { woff[w] = acc; acc += wsum[w]; }
    }
    __syncthreads();

    int thread_excl = g_blocksums[blockIdx.x] + woff[warp] + (inc - tsum);
    int p0 = thread_excl;
    int p1 = p0 + d0;
    int p2 = p1 + d1;
    int p3 = p2 + d2;
    if (e0 + 0 < N_NODES) { g_rowptr[e0 + 0] = p0; g_cursor[e0 + 0] = p0; }
    if (e0 + 1 < N_NODES) { g_rowptr[e0 + 1] = p1; g_cursor[e0 + 1] = p1; }
    if (e0 + 2 < N_NODES) { g_rowptr[e0 + 2] = p2; g_cursor[e0 + 2] = p2; }
    if (e0 + 3 < N_NODES) { g_rowptr[e0 + 3] = p3; g_cursor[e0 + 3] = p3; }
    if (blockIdx.x == 0 && tid == 0) g_rowptr[N_NODES] = E_EDGES;
}

__global__ void scatter_k(const int* __restrict__ src,
                          const int* __restrict__ dst) {
    int e = blockIdx.x * blockDim.x + threadIdx.x;
    if (e < E_EDGES) {
        int pos = atomicAdd(&g_cursor[dst[e]], 1);
        g_csr[pos] = src[e];
    }
}

// ---------------- GEMM: out[i,j] = (sum_k H[i,k] W[k,j]) * n_src[i] ----------------
// 128 threads, 32-row x OUT-col tile, each thread R rows x 4 cols.
template <int IN, int OUT>
__global__ void gemm_scale_k(const float* __restrict__ H,
                             const float* __restrict__ W,
                             float* __restrict__ out) {
    constexpr int CG = OUT / 4;     // col groups
    constexpr int RG = 128 / CG;    // row groups
    constexpr int R = 32 / RG;      // rows per thread
    __shared__ float Hs[32 * IN];

    int tid = threadIdx.x;
    int row0 = blockIdx.x * 32;

    {
        const float4* Hg = reinterpret_cast<const float4*>(H + (size_t)row0 * IN);
        float4* Hs4 = reinterpret_cast<float4*>(Hs);
#pragma unroll
        for (int i = tid; i < 32 * IN / 4; i += 128) Hs4[i] = Hg[i];
    }
    __syncthreads();

    int tx = tid % CG;
    int ty = tid / CG;
    const float* hbase = Hs + (size_t)(ty * R) * IN;

    float acc[R][4];
#pragma unroll
    for (int r = 0; r < R; r++)
#pragma unroll
        for (int c = 0; c < 4; c++) acc[r][c] = 0.f;

    for (int k = 0; k < IN; k += 2) {
        float4 w0 = *reinterpret_cast<const float4*>(W + (size_t)k * OUT + tx * 4);
        float4 w1 = *reinterpret_cast<const float4*>(W + (size_t)(k + 1) * OUT + tx * 4);
#pragma unroll
        for (int r = 0; r < R; r++) {
            float2 hv = *reinterpret_cast<const float2*>(hbase + (size_t)r * IN + k);
            acc[r][0] += hv.x * w0.x + hv.y * w1.x;
            acc[r][1] += hv.x * w0.y + hv.y * w1.y;
            acc[r][2] += hv.x * w0.z + hv.y * w1.z;
            acc[r][3] += hv.x * w0.w + hv.y * w1.w;
        }
    }

#pragma unroll
    for (int r = 0; r < R; r++) {
        int row = row0 + ty * R + r;
        float ns = g_nsrc[row];
        float4 o = make_float4(acc[r][0] * ns, acc[r][1] * ns,
                               acc[r][2] * ns, acc[r][3] * ns);
        *reinterpret_cast<float4*>(out + (size_t)row * OUT + tx * 4) = o;
    }
}

// ---------------- CSR SpMM, fused finalize: h[d] = (sum_src tmp[src]) * n_dst[d] + b ----------------
// warp per dst node, float4 per lane (128 features)
__global__ void spmm_csr128_k(const float* __restrict__ tmp,
                              const float* __restrict__ b,
                              float* __restrict__ h) {
    int w = (blockIdx.x * blockDim.x + threadIdx.x) >> 5;
    int lane = threadIdx.x & 31;
    if (w >= N_NODES) return;
    int beg = g_rowptr[w];
    int end = g_rowptr[w + 1];
    float4 acc = make_float4(0.f, 0.f, 0.f, 0.f);
    int i = beg;
    for (; i + 3 < end; i += 4) {
        int s0 = g_csr[i], s1 = g_csr[i + 1], s2 = g_csr[i + 2], s3 = g_csr[i + 3];
        float4 v0 = *reinterpret_cast<const float4*>(tmp + (size_t)s0 * 128 + lane * 4);
        float4 v1 = *reinterpret_cast<const float4*>(tmp + (size_t)s1 * 128 + lane * 4);
        float4 v2 = *reinterpret_cast<const float4*>(tmp + (size_t)s2 * 128 + lane * 4);
        float4 v3 = *reinterpret_cast<const float4*>(tmp + (size_t)s3 * 128 + lane * 4);
        acc.x += v0.x + v1.x + v2.x + v3.x;
        acc.y += v0.y + v1.y + v2.y + v3.y;
        acc.z += v0.z + v1.z + v2.z + v3.z;
        acc.w += v0.w + v1.w + v2.w + v3.w;
    }
    for (; i < end; i++) {
        int s = g_csr[i];
        float4 v = *reinterpret_cast<const float4*>(tmp + (size_t)s * 128 + lane * 4);
        acc.x += v.x; acc.y += v.y; acc.z += v.z; acc.w += v.w;
    }
    float nd = g_ndst[w];
    float4 bb = *reinterpret_cast<const float4*>(b + lane * 4);
    float4 o = make_float4(acc.x * nd + bb.x, acc.y * nd + bb.y,
                           acc.z * nd + bb.z, acc.w * nd + bb.w);
    *reinterpret_cast<float4*>(h + (size_t)w * 128 + lane * 4) = o;
}

// 64 features, fused finalize + softmax. warp per dst node, float2 per lane.
__global__ void spmm_csr64_softmax_k(const float* __restrict__ tmp,
                                     const float* __restrict__ b,
                                     float* __restrict__ out) {
    int w = (blockIdx.x * blockDim.x + threadIdx.x) >> 5;
    int lane = threadIdx.x & 31;
    if (w >= N_NODES) return;
    int beg = g_rowptr[w];
    int end = g_rowptr[w + 1];
    float2 acc = make_float2(0.f, 0.f);
    int i = beg;
    for (; i + 3 < end; i += 4) {
        int s0 = g_csr[i], s1 = g_csr[i + 1], s2 = g_csr[i + 2], s3 = g_csr[i + 3];
        float2 v0 = *reinterpret_cast<const float2*>(tmp + (size_t)s0 * 64 + lane * 2);
        float2 v1 = *reinterpret_cast<const float2*>(tmp + (size_t)s1 * 64 + lane * 2);
        float2 v2 = *reinterpret_cast<const float2*>(tmp + (size_t)s2 * 64 + lane * 2);
        float2 v3 = *reinterpret_cast<const float2*>(tmp + (size_t)s3 * 64 + lane * 2);
        acc.x += v0.x + v1.x + v2.x + v3.x;
        acc.y += v0.y + v1.y + v2.y + v3.y;
    }
    for (; i < end; i++) {
        int s = g_csr[i];
        float2 v = *reinterpret_cast<const float2*>(tmp + (size_t)s * 64 + lane * 2);
        acc.x += v.x; acc.y += v.y;
    }
    float nd = g_ndst[w];
    float2 bb = *reinterpret_cast<const float2*>(b + lane * 2);
    float a0 = acc.x * nd + bb.x;
    float a1 = acc.y * nd + bb.y;
    float m = fmaxf(a0, a1);
#pragma unroll
    for (int o = 16; o > 0; o >>= 1) m = fmaxf(m, __shfl_xor_sync(0xffffffffu, m, o));
    float e0 = __expf(a0 - m);
    float e1 = __expf(a1 - m);
    float s = e0 + e1;
#pragma unroll
    for (int o = 16; o > 0; o >>= 1) s += __shfl_xor_sync(0xffffffffu, s, o);
    float inv = 1.f / s;
    reinterpret_cast<float2*>(out + (size_t)w * 64)[lane] = make_float2(e0 * inv, e1 * inv);
}

// ---------------- launch ----------------

extern "C" void kernel_launch(void* const* d_in, const int* in_sizes, int n_in,
                              void* d_out, int out_size) {
    const float* x = (const float*)d_in[0];
    const int* src = (const int*)d_in[1];
    const int* dst = (const int*)d_in[2];
    const float* W0 = (const float*)d_in[3];
    const float* b0 = (const float*)d_in[4];
    const float* W1 = (const float*)d_in[5];
    const float* b1 = (const float*)d_in[6];
    const float* W2 = (const float*)d_in[7];
    const float* b2 = (const float*)d_in[8];
    float* out = (float*)d_out;

    float *tmp, *h;
    cudaGetSymbolAddress((void**)&tmp, g_tmp);
    cudaGetSymbolAddress((void**)&h, g_h);

    const int TPB = 256;
    const int nodeBlocks = (N_NODES + TPB - 1) / TPB;
    const int edgeBlocks = (E_EDGES + TPB - 1) / TPB;
    const int nodeWarpBlocks = (int)(((size_t)N_NODES * 32 + TPB - 1) / TPB);

    // degrees, norms, CSR build
    zero_deg_k<<<nodeBlocks, TPB>>>();
    degree_k<<<edgeBlocks, TPB>>>(src, dst);
    norms_k<<<nodeBlocks, TPB>>>();
    blocksum_k<<<SCAN_NB, 256>>>();
    scanblocks_k<<<1, 128>>>();
    localscan_k<<<SCAN_NB, 256>>>();
    scatter_k<<<edgeBlocks, TPB>>>(src, dst);

    // ---- Layer 0: 256 -> 128 ----
    gemm_scale_k<NFEAT, NHID><<<N_NODES / 32, 128>>>(x, W0, tmp);
    spmm_csr128_k<<<nodeWarpBlocks, TPB>>>(tmp, b0, h);

    // ---- Layer 1: 128 -> 128 ----
    gemm_scale_k<NHID, NHID><<<N_NODES / 32, 128>>>(h, W1, tmp);
    spmm_csr128_k<<<nodeWarpBlocks, TPB>>>(tmp, b1, h);

    // ---- Layer 2: 128 -> 64, + softmax ----
    gemm_scale_k<NHID, NCLASS><<<N_NODES / 32, 128>>>(h, W2, tmp);
    spmm_csr64_softmax_k<<<nodeWarpBlocks, TPB>>>(tmp, b2, out);
}

// round 7
// speedup vs baseline: 2.6619x; 1.2236x over previous
#include <cuda_runtime.h>
#include <cuda_bf16.h>
#include <math.h>

#define N_NODES 100000
#define E_EDGES 3200000
#define NFEAT 256
#define NHID 128
#define NCLASS 64

#define SCAN_CHUNK 1024
#define SCAN_NB ((N_NODES + SCAN_CHUNK - 1) / SCAN_CHUNK)   // 98

// Scratch (allocation-free rule: __device__ globals)
__device__ __align__(256) float g_tmp[(size_t)N_NODES * NHID];
__device__ __align__(256) float g_h[(size_t)N_NODES * NHID];
__device__ __align__(256) float g_nsrc[N_NODES];
__device__ __align__(256) float g_ndst[N_NODES];
__device__ __align__(256) int g_degout[N_NODES];
__device__ __align__(256) int g_degin[N_NODES];
__device__ __align__(256) int g_rowptr[N_NODES + 1];
__device__ __align__(256) int g_cursor[N_NODES];
__device__ __align__(256) int g_csr[E_EDGES];
__device__ __align__(256) int g_blocksums[SCAN_NB];

// f32x2 helpers
__device__ __forceinline__ unsigned long long pack2(float lo, float hi) {
    unsigned long long r;
    asm("mov.b64 %0, {%1, %2};" : "=l"(r) : "f"(lo), "f"(hi));
    return r;
}
__device__ __forceinline__ void fma2(unsigned long long& acc,
                                     unsigned long long a,
                                     unsigned long long b) {
    asm("fma.rn.f32x2 %0, %1, %2, %0;" : "+l"(acc) : "l"(a), "l"(b));
}
__device__ __forceinline__ float2 unpack2(unsigned long long v) {
    float lo, hi;
    asm("mov.b64 {%0, %1}, %2;" : "=f"(lo), "=f"(hi) : "l"(v));
    return make_float2(lo, hi);
}

// ---------------- degree / norms ----------------

__global__ void zero_deg_k() {
    int i = blockIdx.x * blockDim.x + threadIdx.x;
    if (i < N_NODES) { g_degout[i] = 0; g_degin[i] = 0; }
}

__global__ void degree_k(const int* __restrict__ src,
                         const int* __restrict__ dst) {
    int e = blockIdx.x * blockDim.x + threadIdx.x;
    if (e < E_EDGES) {
        atomicAdd(&g_degout[src[e]], 1);
        atomicAdd(&g_degin[dst[e]], 1);
    }
}

__global__ void norms_k() {
    int i = blockIdx.x * blockDim.x + threadIdx.x;
    if (i < N_NODES) {
        int dov = g_degout[i];
        int div_ = g_degin[i];
        g_nsrc[i] = rsqrtf((float)(dov > 0 ? dov : 1));
        g_ndst[i] = rsqrtf((float)(div_ > 0 ? div_ : 1));
    }
}

// ---------------- 3-phase exclusive scan of deg_in -> rowptr/cursor ----------------

__global__ void blocksum_k() {
    int base = blockIdx.x * SCAN_CHUNK;
    int tid = threadIdx.x;
    int s = 0;
#pragma unroll
    for (int j = 0; j < 4; j++) {
        int idx = base + tid * 4 + j;
        if (idx < N_NODES) s += g_degin[idx];
    }
#pragma unroll
    for (int o = 16; o > 0; o >>= 1) s += __shfl_xor_sync(0xffffffffu, s, o);
    __shared__ int ws[8];
    if ((tid & 31) == 0) ws[tid >> 5] = s;
    __syncthreads();
    if (tid == 0) {
        int t = 0;
#pragma unroll
        for (int w = 0; w < 8; w++) t += ws[w];
        g_blocksums[blockIdx.x] = t;
    }
}

__global__ void scanblocks_k() {
    __shared__ int s[128];
    int tid = threadIdx.x;
    int v = (tid < SCAN_NB) ? g_blocksums[tid] : 0;
    s[tid] = v;
    __syncthreads();
#pragma unroll
    for (int off = 1; off < 128; off <<= 1) {
        int t = (tid >= off) ? s[tid - off] : 0;
        __syncthreads();
        s[tid] += t;
        __syncthreads();
    }
    if (tid < SCAN_NB) g_blocksums[tid] = s[tid] - v;  // exclusive
}

__global__ void localscan_k() {
    int base = blockIdx.x * SCAN_CHUNK;
    int tid = threadIdx.x;
    int lane = tid & 31;
    int warp = tid >> 5;

    int e0 = base + tid * 4;
    int d0 = (e0 + 0 < N_NODES) ? g_degin[e0 + 0] : 0;
    int d1 = (e0 + 1 < N_NODES) ? g_degin[e0 + 1] : 0;
    int d2 = (e0 + 2 < N_NODES) ? g_degin[e0 + 2] : 0;
    int d3 = (e0 + 3 < N_NODES) ? g_degin[e0 + 3] : 0;
    int tsum = d0 + d1 + d2 + d3;

    int inc = tsum;
#pragma unroll
    for (int o = 1; o < 32; o <<= 1) {
        int t = __shfl_up_sync(0xffffffffu, inc, o);
        if (lane >= o) inc += t;
    }
    __shared__ int wsum[8];
    if (lane == 31) wsum[warp] = inc;
    __syncthreads();
    __shared__ int woff[8];
    if (tid == 0) {
        int acc = 0;
#pragma unroll
        for (int w = 0; w < 8; w++) { woff[w] = acc; acc += wsum[w]; }
    }
    __syncthreads();

    int thread_excl = g_blocksums[blockIdx.x] + woff[warp] + (inc - tsum);
    int p0 = thread_excl;
    int p1 = p0 + d0;
    int p2 = p1 + d1;
    int p3 = p2 + d2;
    if (e0 + 0 < N_NODES) { g_rowptr[e0 + 0] = p0; g_cursor[e0 + 0] = p0; }
    if (e0 + 1 < N_NODES) { g_rowptr[e0 + 1] = p1; g_cursor[e0 + 1] = p1; }
    if (e0 + 2 < N_NODES) { g_rowptr[e0 + 2] = p2; g_cursor[e0 + 2] = p2; }
    if (e0 + 3 < N_NODES) { g_rowptr[e0 + 3] = p3; g_cursor[e0 + 3] = p3; }
    if (blockIdx.x == 0 && tid == 0) g_rowptr[N_NODES] = E_EDGES;
}

__global__ void scatter_k(const int* __restrict__ src,
                          const int* __restrict__ dst) {
    int e = blockIdx.x * blockDim.x + threadIdx.x;
    if (e < E_EDGES) {
        int pos = atomicAdd(&g_cursor[dst[e]], 1);
        g_csr[pos] = src[e];
    }
}

// ---------------- GEMM: out[i,j] = (sum_k H[i,k] W[k,j]) * n_src[i] ----------------
// 128 threads, 32-row x OUT-col tile, each thread R rows x 4 cols.
// Inner math uses packed fma.rn.f32x2 (FFMA2) pairing adjacent output columns.
template <int IN, int OUT>
__global__ void gemm_scale_k(const float* __restrict__ H,
                             const float* __restrict__ W,
                             float* __restrict__ out) {
    constexpr int CG = OUT / 4;     // col groups (thread handles 4 cols = 2 pairs)
    constexpr int RG = 128 / CG;    // row groups
    constexpr int R = 32 / RG;      // rows per thread
    __shared__ float Hs[32 * IN];

    int tid = threadIdx.x;
    int row0 = blockIdx.x * 32;

    {
        const float4* Hg = reinterpret_cast<const float4*>(H + (size_t)row0 * IN);
        float4* Hs4 = reinterpret_cast<float4*>(Hs);
#pragma unroll
        for (int i = tid; i < 32 * IN / 4; i += 128) Hs4[i] = Hg[i];
    }
    __syncthreads();

    int tx = tid % CG;
    int ty = tid / CG;
    const float* hbase = Hs + (size_t)(ty * R) * IN;

    // acc[r][p]: p=0 -> cols (4tx, 4tx+1), p=1 -> cols (4tx+2, 4tx+3)
    unsigned long long acc[R][2];
#pragma unroll
    for (int r = 0; r < R; r++) { acc[r][0] = 0ull; acc[r][1] = 0ull; }

    for (int k = 0; k < IN; k += 2) {
        float4 w0 = *reinterpret_cast<const float4*>(W + (size_t)k * OUT + tx * 4);
        float4 w1 = *reinterpret_cast<const float4*>(W + (size_t)(k + 1) * OUT + tx * 4);
        unsigned long long w0a = pack2(w0.x, w0.y);
        unsigned long long w0b = pack2(w0.z, w0.w);
        unsigned long long w1a = pack2(w1.x, w1.y);
        unsigned long long w1b = pack2(w1.z, w1.w);
#pragma unroll
        for (int r = 0; r < R; r++) {
            float2 hv = *reinterpret_cast<const float2*>(hbase + (size_t)r * IN + k);
            unsigned long long hx = pack2(hv.x, hv.x);
            unsigned long long hy = pack2(hv.y, hv.y);
            fma2(acc[r][0], hx, w0a);
            fma2(acc[r][1], hx, w0b);
            fma2(acc[r][0], hy, w1a);
            fma2(acc[r][1], hy, w1b);
        }
    }

#pragma unroll
    for (int r = 0; r < R; r++) {
        int row = row0 + ty * R + r;
        float ns = g_nsrc[row];
        float2 lo = unpack2(acc[r][0]);
        float2 hi = unpack2(acc[r][1]);
        float4 o = make_float4(lo.x * ns, lo.y * ns, hi.x * ns, hi.y * ns);
        *reinterpret_cast<float4*>(out + (size_t)row * OUT + tx * 4) = o;
    }
}

// ---------------- CSR SpMM, fused finalize: h[d] = (sum_src tmp[src]) * n_dst[d] + b ----------------
// warp per dst node, float4 per lane (128 features)
__global__ void spmm_csr128_k(const float* __restrict__ tmp,
                              const float* __restrict__ b,
                              float* __restrict__ h) {
    int w = (blockIdx.x * blockDim.x + threadIdx.x) >> 5;
    int lane = threadIdx.x & 31;
    if (w >= N_NODES) return;
    int beg = g_rowptr[w];
    int end = g_rowptr[w + 1];
    float4 acc = make_float4(0.f, 0.f, 0.f, 0.f);
    int i = beg;
    for (; i + 3 < end; i += 4) {
        int s0 = g_csr[i], s1 = g_csr[i + 1], s2 = g_csr[i + 2], s3 = g_csr[i + 3];
        float4 v0 = *reinterpret_cast<const float4*>(tmp + (size_t)s0 * 128 + lane * 4);
        float4 v1 = *reinterpret_cast<const float4*>(tmp + (size_t)s1 * 128 + lane * 4);
        float4 v2 = *reinterpret_cast<const float4*>(tmp + (size_t)s2 * 128 + lane * 4);
        float4 v3 = *reinterpret_cast<const float4*>(tmp + (size_t)s3 * 128 + lane * 4);
        acc.x += v0.x + v1.x + v2.x + v3.x;
        acc.y += v0.y + v1.y + v2.y + v3.y;
        acc.z += v0.z + v1.z + v2.z + v3.z;
        acc.w += v0.w + v1.w + v2.w + v3.w;
    }
    for (; i < end; i++) {
        int s = g_csr[i];
        float4 v = *reinterpret_cast<const float4*>(tmp + (size_t)s * 128 + lane * 4);
        acc.x += v.x; acc.y += v.y; acc.z += v.z; acc.w += v.w;
    }
    float nd = g_ndst[w];
    float4 bb = *reinterpret_cast<const float4*>(b + lane * 4);
    float4 o = make_float4(acc.x * nd + bb.x, acc.y * nd + bb.y,
                           acc.z * nd + bb.z, acc.w * nd + bb.w);
    *reinterpret_cast<float4*>(h + (size_t)w * 128 + lane * 4) = o;
}

// 64 features, fused finalize + softmax. warp per dst node, float2 per lane.
__global__ void spmm_csr64_softmax_k(const float* __restrict__ tmp,
                                     const float* __restrict__ b,
                                     float* __restrict__ out) {
    int w = (blockIdx.x * blockDim.x + threadIdx.x) >> 5;
    int lane = threadIdx.x & 31;
    if (w >= N_NODES) return;
    int beg = g_rowptr[w];
    int end = g_rowptr[w + 1];
    float2 acc = make_float2(0.f, 0.f);
    int i = beg;
    for (; i + 3 < end; i += 4) {
        int s0 = g_csr[i], s1 = g_csr[i + 1], s2 = g_csr[i + 2], s3 = g_csr[i + 3];
        float2 v0 = *reinterpret_cast<const float2*>(tmp + (size_t)s0 * 64 + lane * 2);
        float2 v1 = *reinterpret_cast<const float2*>(tmp + (size_t)s1 * 64 + lane * 2);
        float2 v2 = *reinterpret_cast<const float2*>(tmp + (size_t)s2 * 64 + lane * 2);
        float2 v3 = *reinterpret_cast<const float2*>(tmp + (size_t)s3 * 64 + lane * 2);
        acc.x += v0.x + v1.x + v2.x + v3.x;
        acc.y += v0.y + v1.y + v2.y + v3.y;
    }
    for (; i < end; i++) {
        int s = g_csr[i];
        float2 v = *reinterpret_cast<const float2*>(tmp + (size_t)s * 64 + lane * 2);
        acc.x += v.x; acc.y += v.y;
    }
    float nd = g_ndst[w];
    float2 bb = *reinterpret_cast<const float2*>(b + lane * 2);
    float a0 = acc.x * nd + bb.x;
    float a1 = acc.y * nd + bb.y;
    float m = fmaxf(a0, a1);
#pragma unroll
    for (int o = 16; o > 0; o >>= 1) m = fmaxf(m, __shfl_xor_sync(0xffffffffu, m, o));
    float e0 = __expf(a0 - m);
    float e1 = __expf(a1 - m);
    float s = e0 + e1;
#pragma unroll
    for (int o = 16; o > 0; o >>= 1) s += __shfl_xor_sync(0xffffffffu, s, o);
    float inv = 1.f / s;
    reinterpret_cast<float2*>(out + (size_t)w * 64)[lane] = make_float2(e0 * inv, e1 * inv);
}

// ---------------- launch ----------------

extern "C" void kernel_launch(void* const* d_in, const int* in_sizes, int n_in,
                              void* d_out, int out_size) {
    const float* x = (const float*)d_in[0];
    const int* src = (const int*)d_in[1];
    const int* dst = (const int*)d_in[2];
    const float* W0 = (const float*)d_in[3];
    const float* b0 = (const float*)d_in[4];
    const float* W1 = (const float*)d_in[5];
    const float* b1 = (const float*)d_in[6];
    const float* W2 = (const float*)d_in[7];
    const float* b2 = (const float*)d_in[8];
    float* out = (float*)d_out;

    float *tmp, *h;
    cudaGetSymbolAddress((void**)&tmp, g_tmp);
    cudaGetSymbolAddress((void**)&h, g_h);

    const int TPB = 256;
    const int nodeBlocks = (N_NODES + TPB - 1) / TPB;
    const int edgeBlocks = (E_EDGES + TPB - 1) / TPB;
    const int nodeWarpBlocks = (int)(((size_t)N_NODES * 32 + TPB - 1) / TPB);

    // degrees, norms, CSR build
    zero_deg_k<<<nodeBlocks, TPB>>>();
    degree_k<<<edgeBlocks, TPB>>>(src, dst);
    norms_k<<<nodeBlocks, TPB>>>();
    blocksum_k<<<SCAN_NB, 256>>>();
    scanblocks_k<<<1, 128>>>();
    localscan_k<<<SCAN_NB, 256>>>();
    scatter_k<<<edgeBlocks, TPB>>>(src, dst);

    // ---- Layer 0: 256 -> 128 ----
    gemm_scale_k<NFEAT, NHID><<<N_NODES / 32, 128>>>(x, W0, tmp);
    spmm_csr128_k<<<nodeWarpBlocks, TPB>>>(tmp, b0, h);

    // ---- Layer 1: 128 -> 128 ----
    gemm_scale_k<NHID, NHID><<<N_NODES / 32, 128>>>(h, W1, tmp);
    spmm_csr128_k<<<nodeWarpBlocks, TPB>>>(tmp, b1, h);

    // ---- Layer 2: 128 -> 64, + softmax ----
    gemm_scale_k<NHID, NCLASS><<<N_NODES / 32, 128>>>(h, W2, tmp);
    spmm_csr64_softmax_k<<<nodeWarpBlocks, TPB>>>(tmp, b2, out);
}

// round 9
// speedup vs baseline: 2.7427x; 1.0303x over previous
#include <cuda_runtime.h>
#include <cuda_bf16.h>
#include <math.h>

#define N_NODES 100000
#define E_EDGES 3200000
#define NFEAT 256
#define NHID 128
#define NCLASS 64

#define SCAN_CHUNK 1024
#define SCAN_NB ((N_NODES + SCAN_CHUNK - 1) / SCAN_CHUNK)   // 98

// Scratch (allocation-free rule: __device__ globals)
__device__ __align__(256) float g_tmp[(size_t)N_NODES * NHID];
__device__ __align__(256) float g_h[(size_t)N_NODES * NHID];
__device__ __align__(256) float g_nsrc[N_NODES];
__device__ __align__(256) float g_ndst[N_NODES];
__device__ __align__(256) int g_degout[N_NODES];
__device__ __align__(256) int g_degin[N_NODES];
__device__ __align__(256) int g_rowptr[N_NODES + 1];
__device__ __align__(256) int g_cursor[N_NODES];
__device__ __align__(256) int g_csr[E_EDGES];
__device__ __align__(256) int g_blocksums[SCAN_NB];

// f32x2 helpers
__device__ __forceinline__ unsigned long long pack2(float lo, float hi) {
    unsigned long long r;
    asm("mov.b64 %0, {%1, %2};" : "=l"(r) : "f"(lo), "f"(hi));
    return r;
}
__device__ __forceinline__ void fma2(unsigned long long& acc,
                                     unsigned long long a,
                                     unsigned long long b) {
    asm("fma.rn.f32x2 %0, %1, %2, %0;" : "+l"(acc) : "l"(a), "l"(b));
}
__device__ __forceinline__ float2 unpack2(unsigned long long v) {
    float lo, hi;
    asm("mov.b64 {%0, %1}, %2;" : "=f"(lo), "=f"(hi) : "l"(v));
    return make_float2(lo, hi);
}

// ---------------- degree / norms ----------------

__global__ void zero_deg_k() {
    int i = blockIdx.x * blockDim.x + threadIdx.x;
    if (i < N_NODES) { g_degout[i] = 0; g_degin[i] = 0; }
}

__global__ void degree_k(const int* __restrict__ src,
                         const int* __restrict__ dst) {
    int e = blockIdx.x * blockDim.x + threadIdx.x;
    if (e < E_EDGES) {
        atomicAdd(&g_degout[src[e]], 1);
        atomicAdd(&g_degin[dst[e]], 1);
    }
}

__global__ void norms_k() {
    int i = blockIdx.x * blockDim.x + threadIdx.x;
    if (i < N_NODES) {
        int dov = g_degout[i];
        int div_ = g_degin[i];
        g_nsrc[i] = rsqrtf((float)(dov > 0 ? dov : 1));
        g_ndst[i] = rsqrtf((float)(div_ > 0 ? div_ : 1));
    }
}

// ---------------- 3-phase exclusive scan of deg_in -> rowptr/cursor ----------------

__global__ void blocksum_k() {
    int base = blockIdx.x * SCAN_CHUNK;
    int tid = threadIdx.x;
    int s = 0;
#pragma unroll
    for (int j = 0; j < 4; j++) {
        int idx = base + tid * 4 + j;
        if (idx < N_NODES) s += g_degin[idx];
    }
#pragma unroll
    for (int o = 16; o > 0; o >>= 1) s += __shfl_xor_sync(0xffffffffu, s, o);
    __shared__ int ws[8];
    if ((tid & 31) == 0) ws[tid >> 5] = s;
    __syncthreads();
    if (tid == 0) {
        int t = 0;
#pragma unroll
        for (int w = 0; w < 8; w++) t += ws[w];
        g_blocksums[blockIdx.x] = t;
    }
}

__global__ void scanblocks_k() {
    __shared__ int s[128];
    int tid = threadIdx.x;
    int v = (tid < SCAN_NB) ? g_blocksums[tid] : 0;
    s[tid] = v;
    __syncthreads();
#pragma unroll
    for (int off = 1; off < 128; off <<= 1) {
        int t = (tid >= off) ? s[tid - off] : 0;
        __syncthreads();
        s[tid] += t;
        __syncthreads();
    }
    if (tid < SCAN_NB) g_blocksums[tid] = s[tid] - v;  // exclusive
}

__global__ void localscan_k() {
    int base = blockIdx.x * SCAN_CHUNK;
    int tid = threadIdx.x;
    int lane = tid & 31;
    int warp = tid >> 5;

    int e0 = base + tid * 4;
    int d0 = (e0 + 0 < N_NODES) ? g_degin[e0 + 0] : 0;
    int d1 = (e0 + 1 < N_NODES) ? g_degin[e0 + 1] : 0;
    int d2 = (e0 + 2 < N_NODES) ? g_degin[e0 + 2] : 0;
    int d3 = (e0 + 3 < N_NODES) ? g_degin[e0 + 3] : 0;
    int tsum = d0 + d1 + d2 + d3;

    int inc = tsum;
#pragma unroll
    for (int o = 1; o < 32; o <<= 1) {
        int t = __shfl_up_sync(0xffffffffu, inc, o);
        if (lane >= o) inc += t;
    }
    __shared__ int wsum[8];
    if (lane == 31) wsum[warp] = inc;
    __syncthreads();
    __shared__ int woff[8];
    if (tid == 0) {
        int acc = 0;
#pragma unroll
        for (int w = 0; w < 8; w++) { woff[w] = acc; acc += wsum[w]; }
    }
    __syncthreads();

    int thread_excl = g_blocksums[blockIdx.x] + woff[warp] + (inc - tsum);
    int p0 = thread_excl;
    int p1 = p0 + d0;
    int p2 = p1 + d1;
    int p3 = p2 + d2;
    if (e0 + 0 < N_NODES) { g_rowptr[e0 + 0] = p0; g_cursor[e0 + 0] = p0; }
    if (e0 + 1 < N_NODES) { g_rowptr[e0 + 1] = p1; g_cursor[e0 + 1] = p1; }
    if (e0 + 2 < N_NODES) { g_rowptr[e0 + 2] = p2; g_cursor[e0 + 2] = p2; }
    if (e0 + 3 < N_NODES) { g_rowptr[e0 + 3] = p3; g_cursor[e0 + 3] = p3; }
    if (blockIdx.x == 0 && tid == 0) g_rowptr[N_NODES] = E_EDGES;
}

__global__ void scatter_k(const int* __restrict__ src,
                          const int* __restrict__ dst) {
    int e = blockIdx.x * blockDim.x + threadIdx.x;
    if (e < E_EDGES) {
        int pos = atomicAdd(&g_cursor[dst[e]], 1);
        g_csr[pos] = src[e];
    }
}

// ---------------- GEMM: out[i,j] = (sum_k H[i,k] W[k,j]) [* n_src[i] if SCALE] ----------------
// 128 threads, 32-row x OUT-col tile, each thread R rows x 4 cols. FFMA2 inner math.
template <int IN, int OUT, bool SCALE>
__global__ void gemm_scale_k(const float* __restrict__ H,
                             const float* __restrict__ W,
                             float* __restrict__ out) {
    constexpr int CG = OUT / 4;     // col groups (thread handles 4 cols = 2 pairs)
    constexpr int RG = 128 / CG;    // row groups
    constexpr int R = 32 / RG;      // rows per thread
    __shared__ float Hs[32 * IN];

    int tid = threadIdx.x;
    int row0 = blockIdx.x * 32;

    {
        const float4* Hg = reinterpret_cast<const float4*>(H + (size_t)row0 * IN);
        float4* Hs4 = reinterpret_cast<float4*>(Hs);
#pragma unroll
        for (int i = tid; i < 32 * IN / 4; i += 128) Hs4[i] = Hg[i];
    }
    __syncthreads();

    int tx = tid % CG;
    int ty = tid / CG;
    const float* hbase = Hs + (size_t)(ty * R) * IN;

    unsigned long long acc[R][2];
#pragma unroll
    for (int r = 0; r < R; r++) { acc[r][0] = 0ull; acc[r][1] = 0ull; }

    for (int k = 0; k < IN; k += 2) {
        float4 w0 = *reinterpret_cast<const float4*>(W + (size_t)k * OUT + tx * 4);
        float4 w1 = *reinterpret_cast<const float4*>(W + (size_t)(k + 1) * OUT + tx * 4);
        unsigned long long w0a = pack2(w0.x, w0.y);
        unsigned long long w0b = pack2(w0.z, w0.w);
        unsigned long long w1a = pack2(w1.x, w1.y);
        unsigned long long w1b = pack2(w1.z, w1.w);
#pragma unroll
        for (int r = 0; r < R; r++) {
            float2 hv = *reinterpret_cast<const float2*>(hbase + (size_t)r * IN + k);
            unsigned long long hx = pack2(hv.x, hv.x);
            unsigned long long hy = pack2(hv.y, hv.y);
            fma2(acc[r][0], hx, w0a);
            fma2(acc[r][1], hx, w0b);
            fma2(acc[r][0], hy, w1a);
            fma2(acc[r][1], hy, w1b);
        }
    }

#pragma unroll
    for (int r = 0; r < R; r++) {
        int row = row0 + ty * R + r;
        float ns = SCALE ? g_nsrc[row] : 1.0f;
        float2 lo = unpack2(acc[r][0]);
        float2 hi = unpack2(acc[r][1]);
        float4 o = make_float4(lo.x * ns, lo.y * ns, hi.x * ns, hi.y * ns);
        *reinterpret_cast<float4*>(out + (size_t)row * OUT + tx * 4) = o;
    }
}

// ---------------- CSR SpMM, fused finalize: h[d] = (sum_src tmp[src]*[nsrc]) * n_dst[d] + b ----
// warp per dst node, float4 per lane (128 features). SRCSCALE: multiply each
// gathered row by n_src[s] (used when the producing GEMM skipped the scaling).
template <bool SRCSCALE>
__global__ void spmm_csr128_k(const float* __restrict__ tmp,
                              const float* __restrict__ b,
                              float* __restrict__ h) {
    int w = (blockIdx.x * blockDim.x + threadIdx.x) >> 5;
    int lane = threadIdx.x & 31;
    if (w >= N_NODES) return;
    int beg = g_rowptr[w];
    int end = g_rowptr[w + 1];
    float4 acc = make_float4(0.f, 0.f, 0.f, 0.f);
    int i = beg;
    for (; i + 3 < end; i += 4) {
        int s0 = g_csr[i], s1 = g_csr[i + 1], s2 = g_csr[i + 2], s3 = g_csr[i + 3];
        float4 v0 = *reinterpret_cast<const float4*>(tmp + (size_t)s0 * 128 + lane * 4);
        float4 v1 = *reinterpret_cast<const float4*>(tmp + (size_t)s1 * 128 + lane * 4);
        float4 v2 = *reinterpret_cast<const float4*>(tmp + (size_t)s2 * 128 + lane * 4);
        float4 v3 = *reinterpret_cast<const float4*>(tmp + (size_t)s3 * 128 + lane * 4);
        if (SRCSCALE) {
            float n0 = __ldg(&g_nsrc[s0]), n1 = __ldg(&g_nsrc[s1]);
            float n2 = __ldg(&g_nsrc[s2]), n3 = __ldg(&g_nsrc[s3]);
            acc.x += v0.x * n0 + v1.x * n1 + v2.x * n2 + v3.x * n3;
            acc.y += v0.y * n0 + v1.y * n1 + v2.y * n2 + v3.y * n3;
            acc.z += v0.z * n0 + v1.z * n1 + v2.z * n2 + v3.z * n3;
            acc.w += v0.w * n0 + v1.w * n1 + v2.w * n2 + v3.w * n3;
        } else {
            acc.x += v0.x + v1.x + v2.x + v3.x;
            acc.y += v0.y + v1.y + v2.y + v3.y;
            acc.z += v0.z + v1.z + v2.z + v3.z;
            acc.w += v0.w + v1.w + v2.w + v3.w;
        }
    }
    for (; i < end; i++) {
        int s = g_csr[i];
        float4 v = *reinterpret_cast<const float4*>(tmp + (size_t)s * 128 + lane * 4);
        float ns = SRCSCALE ? __ldg(&g_nsrc[s]) : 1.0f;
        acc.x += v.x * ns; acc.y += v.y * ns; acc.z += v.z * ns; acc.w += v.w * ns;
    }
    float nd = g_ndst[w];
    float4 bb = *reinterpret_cast<const float4*>(b + lane * 4);
    float4 o = make_float4(acc.x * nd + bb.x, acc.y * nd + bb.y,
                           acc.z * nd + bb.z, acc.w * nd + bb.w);
    *reinterpret_cast<float4*>(h + (size_t)w * 128 + lane * 4) = o;
}

// 64 features, fused finalize + softmax. warp per dst node, float2 per lane.
__global__ void spmm_csr64_softmax_k(const float* __restrict__ tmp,
                                     const float* __restrict__ b,
                                     float* __restrict__ out) {
    int w = (blockIdx.x * blockDim.x + threadIdx.x) >> 5;
    int lane = threadIdx.x & 31;
    if (w >= N_NODES) return;
    int beg = g_rowptr[w];
    int end = g_rowptr[w + 1];
    float2 acc = make_float2(0.f, 0.f);
    int i = beg;
    for (; i + 3 < end; i += 4) {
        int s0 = g_csr[i], s1 = g_csr[i + 1], s2 = g_csr[i + 2], s3 = g_csr[i + 3];
        float2 v0 = *reinterpret_cast<const float2*>(tmp + (size_t)s0 * 64 + lane * 2);
        float2 v1 = *reinterpret_cast<const float2*>(tmp + (size_t)s1 * 64 + lane * 2);
        float2 v2 = *reinterpret_cast<const float2*>(tmp + (size_t)s2 * 64 + lane * 2);
        float2 v3 = *reinterpret_cast<const float2*>(tmp + (size_t)s3 * 64 + lane * 2);
        acc.x += v0.x + v1.x + v2.x + v3.x;
        acc.y += v0.y + v1.y + v2.y + v3.y;
    }
    for (; i < end; i++) {
        int s = g_csr[i];
        float2 v = *reinterpret_cast<const float2*>(tmp + (size_t)s * 64 + lane * 2);
        acc.x += v.x; acc.y += v.y;
    }
    float nd = g_ndst[w];
    float2 bb = *reinterpret_cast<const float2*>(b + lane * 2);
    float a0 = acc.x * nd + bb.x;
    float a1 = acc.y * nd + bb.y;
    float m = fmaxf(a0, a1);
#pragma unroll
    for (int o = 16; o > 0; o >>= 1) m = fmaxf(m, __shfl_xor_sync(0xffffffffu, m, o));
    float e0 = __expf(a0 - m);
    float e1 = __expf(a1 - m);
    float s = e0 + e1;
#pragma unroll
    for (int o = 16; o > 0; o >>= 1) s += __shfl_xor_sync(0xffffffffu, s, o);
    float inv = 1.f / s;
    reinterpret_cast<float2*>(out + (size_t)w * 64)[lane] = make_float2(e0 * inv, e1 * inv);
}

// ---------------- launch ----------------

extern "C" void kernel_launch(void* const* d_in, const int* in_sizes, int n_in,
                              void* d_out, int out_size) {
    const float* x = (const float*)d_in[0];
    const int* src = (const int*)d_in[1];
    const int* dst = (const int*)d_in[2];
    const float* W0 = (const float*)d_in[3];
    const float* b0 = (const float*)d_in[4];
    const float* W1 = (const float*)d_in[5];
    const float* b1 = (const float*)d_in[6];
    const float* W2 = (const float*)d_in[7];
    const float* b2 = (const float*)d_in[8];
    float* out = (float*)d_out;

    float *tmp, *h;
    cudaGetSymbolAddress((void**)&tmp, g_tmp);
    cudaGetSymbolAddress((void**)&h, g_h);

    // one-time host objects (no device memory)
    static cudaStream_t s_side = nullptr;
    static cudaEvent_t s_fork = nullptr, s_join = nullptr;
    if (s_side == nullptr) {
        cudaStreamCreateWithFlags(&s_side, cudaStreamNonBlocking);
        cudaEventCreateWithFlags(&s_fork, cudaEventDisableTiming);
        cudaEventCreateWithFlags(&s_join, cudaEventDisableTiming);
    }

    const int TPB = 256;
    const int nodeBlocks = (N_NODES + TPB - 1) / TPB;
    const int edgeBlocks = (E_EDGES + TPB - 1) / TPB;
    const int nodeWarpBlocks = (int)(((size_t)N_NODES * 32 + TPB - 1) / TPB);

    // fork: layer-0 GEMM (unscaled — independent of degree/norms) on side stream
    cudaEventRecord(s_fork, 0);
    cudaStreamWaitEvent(s_side, s_fork, 0);
    gemm_scale_k<NFEAT, NHID, false><<<N_NODES / 32, 128, 0, s_side>>>(x, W0, tmp);
    cudaEventRecord(s_join, s_side);

    // CSR build chain on main stream (concurrent with GEMM0)
    zero_deg_k<<<nodeBlocks, TPB>>>();
    degree_k<<<edgeBlocks, TPB>>>(src, dst);
    norms_k<<<nodeBlocks, TPB>>>();
    blocksum_k<<<SCAN_NB, 256>>>();
    scanblocks_k<<<1, 128>>>();
    localscan_k<<<SCAN_NB, 256>>>();
    scatter_k<<<edgeBlocks, TPB>>>(src, dst);

    // join
    cudaStreamWaitEvent(0, s_join, 0);

    // ---- Layer 0: SpMM applies n_src per gathered row ----
    spmm_csr128_k<true><<<nodeWarpBlocks, TPB>>>(tmp, b0, h);

    // ---- Layer 1: 128 -> 128 ----
    gemm_scale_k<NHID, NHID, true><<<N_NODES / 32, 128>>>(h, W1, tmp);
    spmm_csr128_k<false><<<nodeWarpBlocks, TPB>>>(tmp, b1, h);

    // ---- Layer 2: 128 -> 64, + softmax ----
    gemm_scale_k<NHID, NCLASS, true><<<N_NODES / 32, 128>>>(h, W2, tmp);
    spmm_csr64_softmax_k<<<nodeWarpBlocks, TPB>>>(tmp, b2, out);
}

// round 10
// speedup vs baseline: 2.9299x; 1.0683x over previous
#include <cuda_runtime.h>
#include <cuda_bf16.h>
#include <cuda_fp16.h>
#include <math.h>

#define N_NODES 100000
#define E_EDGES 3200000
#define NFEAT 256
#define NHID 128
#define NCLASS 64

#define SCAN_CHUNK 1024
#define SCAN_NB ((N_NODES + SCAN_CHUNK - 1) / SCAN_CHUNK)   // 98

// Scratch (allocation-free rule: __device__ globals)
__device__ __align__(256) __half g_tmph[(size_t)N_NODES * NHID];   // fp16 activations
__device__ __align__(256) float g_h[(size_t)N_NODES * NHID];
__device__ __align__(256) float g_nsrc[N_NODES];
__device__ __align__(256) float g_ndst[N_NODES];
__device__ __align__(256) int g_degout[N_NODES];
__device__ __align__(256) int g_degin[N_NODES];
__device__ __align__(256) int g_rowptr[N_NODES + 1];
__device__ __align__(256) int g_cursor[N_NODES];
__device__ __align__(256) int g_csr[E_EDGES];
__device__ __align__(256) int g_blocksums[SCAN_NB];

// f32x2 helpers
__device__ __forceinline__ unsigned long long pack2(float lo, float hi) {
    unsigned long long r;
    asm("mov.b64 %0, {%1, %2};" : "=l"(r) : "f"(lo), "f"(hi));
    return r;
}
__device__ __forceinline__ void fma2(unsigned long long& acc,
                                     unsigned long long a,
                                     unsigned long long b) {
    asm("fma.rn.f32x2 %0, %1, %2, %0;" : "+l"(acc) : "l"(a), "l"(b));
}
__device__ __forceinline__ float2 unpack2(unsigned long long v) {
    float lo, hi;
    asm("mov.b64 {%0, %1}, %2;" : "=f"(lo), "=f"(hi) : "l"(v));
    return make_float2(lo, hi);
}

// ---------------- degree / norms ----------------

__global__ void zero_deg_k() {
    int i = blockIdx.x * blockDim.x + threadIdx.x;
    if (i < N_NODES) { g_degout[i] = 0; g_degin[i] = 0; }
}

__global__ void degree_k(const int* __restrict__ src,
                         const int* __restrict__ dst) {
    int e = blockIdx.x * blockDim.x + threadIdx.x;
    if (e < E_EDGES) {
        atomicAdd(&g_degout[src[e]], 1);
        atomicAdd(&g_degin[dst[e]], 1);
    }
}

__global__ void norms_k() {
    int i = blockIdx.x * blockDim.x + threadIdx.x;
    if (i < N_NODES) {
        int dov = g_degout[i];
        int div_ = g_degin[i];
        g_nsrc[i] = rsqrtf((float)(dov > 0 ? dov : 1));
        g_ndst[i] = rsqrtf((float)(div_ > 0 ? div_ : 1));
    }
}

// ---------------- 3-phase exclusive scan of deg_in -> rowptr/cursor ----------------

__global__ void blocksum_k() {
    int base = blockIdx.x * SCAN_CHUNK;
    int tid = threadIdx.x;
    int s = 0;
#pragma unroll
    for (int j = 0; j < 4; j++) {
        int idx = base + tid * 4 + j;
        if (idx < N_NODES) s += g_degin[idx];
    }
#pragma unroll
    for (int o = 16; o > 0; o >>= 1) s += __shfl_xor_sync(0xffffffffu, s, o);
    __shared__ int ws[8];
    if ((tid & 31) == 0) ws[tid >> 5] = s;
    __syncthreads();
    if (tid == 0) {
        int t = 0;
#pragma unroll
        for (int w = 0; w < 8; w++) t += ws[w];
        g_blocksums[blockIdx.x] = t;
    }
}

__global__ void scanblocks_k() {
    __shared__ int s[128];
    int tid = threadIdx.x;
    int v = (tid < SCAN_NB) ? g_blocksums[tid] : 0;
    s[tid] = v;
    __syncthreads();
#pragma unroll
    for (int off = 1; off < 128; off <<= 1) {
        int t = (tid >= off) ? s[tid - off] : 0;
        __syncthreads();
        s[tid] += t;
        __syncthreads();
    }
    if (tid < SCAN_NB) g_blocksums[tid] = s[tid] - v;  // exclusive
}

__global__ void localscan_k() {
    int base = blockIdx.x * SCAN_CHUNK;
    int tid = threadIdx.x;
    int lane = tid & 31;
    int warp = tid >> 5;

    int e0 = base + tid * 4;
    int d0 = (e0 + 0 < N_NODES) ? g_degin[e0 + 0] : 0;
    int d1 = (e0 + 1 < N_NODES) ? g_degin[e0 + 1] : 0;
    int d2 = (e0 + 2 < N_NODES) ? g_degin[e0 + 2] : 0;
    int d3 = (e0 + 3 < N_NODES) ? g_degin[e0 + 3] : 0;
    int tsum = d0 + d1 + d2 + d3;

    int inc = tsum;
#pragma unroll
    for (int o = 1; o < 32; o <<= 1) {
        int t = __shfl_up_sync(0xffffffffu, inc, o);
        if (lane >= o) inc += t;
    }
    __shared__ int wsum[8];
    if (lane == 31) wsum[warp] = inc;
    __syncthreads();
    __shared__ int woff[8];
    if (tid == 0) {
        int acc = 0;
#pragma unroll
        for (int w = 0; w < 8; w++) { woff[w] = acc; acc += wsum[w]; }
    }
    __syncthreads();

    int thread_excl = g_blocksums[blockIdx.x] + woff[warp] + (inc - tsum);
    int p0 = thread_excl;
    int p1 = p0 + d0;
    int p2 = p1 + d1;
    int p3 = p2 + d2;
    if (e0 + 0 < N_NODES) { g_rowptr[e0 + 0] = p0; g_cursor[e0 + 0] = p0; }
    if (e0 + 1 < N_NODES) { g_rowptr[e0 + 1] = p1; g_cursor[e0 + 1] = p1; }
    if (e0 + 2 < N_NODES) { g_rowptr[e0 + 2] = p2; g_cursor[e0 + 2] = p2; }
    if (e0 + 3 < N_NODES) { g_rowptr[e0 + 3] = p3; g_cursor[e0 + 3] = p3; }
    if (blockIdx.x == 0 && tid == 0) g_rowptr[N_NODES] = E_EDGES;
}

__global__ void scatter_k(const int* __restrict__ src,
                          const int* __restrict__ dst) {
    int e = blockIdx.x * blockDim.x + threadIdx.x;
    if (e < E_EDGES) {
        int pos = atomicAdd(&g_cursor[dst[e]], 1);
        g_csr[pos] = src[e];
    }
}

// ---------------- GEMM: tmp16[i,j] = (sum_k H[i,k] W[k,j]) [* n_src[i] if SCALE] ------------
// fp32 accumulate (FFMA2), fp16 packed output. 128 threads, 32-row tile.
template <int IN, int OUT, bool SCALE>
__global__ void gemm_h_k(const float* __restrict__ H,
                         const float* __restrict__ W,
                         __half* __restrict__ out) {
    constexpr int CG = OUT / 4;     // col groups (thread handles 4 cols = 2 pairs)
    constexpr int RG = 128 / CG;    // row groups
    constexpr int R = 32 / RG;      // rows per thread
    __shared__ float Hs[32 * IN];

    int tid = threadIdx.x;
    int row0 = blockIdx.x * 32;

    {
        const float4* Hg = reinterpret_cast<const float4*>(H + (size_t)row0 * IN);
        float4* Hs4 = reinterpret_cast<float4*>(Hs);
#pragma unroll
        for (int i = tid; i < 32 * IN / 4; i += 128) Hs4[i] = Hg[i];
    }
    __syncthreads();

    int tx = tid % CG;
    int ty = tid / CG;
    const float* hbase = Hs + (size_t)(ty * R) * IN;

    unsigned long long acc[R][2];
#pragma unroll
    for (int r = 0; r < R; r++) { acc[r][0] = 0ull; acc[r][1] = 0ull; }

    for (int k = 0; k < IN; k += 2) {
        float4 w0 = *reinterpret_cast<const float4*>(W + (size_t)k * OUT + tx * 4);
        float4 w1 = *reinterpret_cast<const float4*>(W + (size_t)(k + 1) * OUT + tx * 4);
        unsigned long long w0a = pack2(w0.x, w0.y);
        unsigned long long w0b = pack2(w0.z, w0.w);
        unsigned long long w1a = pack2(w1.x, w1.y);
        unsigned long long w1b = pack2(w1.z, w1.w);
#pragma unroll
        for (int r = 0; r < R; r++) {
            float2 hv = *reinterpret_cast<const float2*>(hbase + (size_t)r * IN + k);
            unsigned long long hx = pack2(hv.x, hv.x);
            unsigned long long hy = pack2(hv.y, hv.y);
            fma2(acc[r][0], hx, w0a);
            fma2(acc[r][1], hx, w0b);
            fma2(acc[r][0], hy, w1a);
            fma2(acc[r][1], hy, w1b);
        }
    }

#pragma unroll
    for (int r = 0; r < R; r++) {
        int row = row0 + ty * R + r;
        float ns = SCALE ? g_nsrc[row] : 1.0f;
        float2 lo = unpack2(acc[r][0]);
        float2 hi = unpack2(acc[r][1]);
        __half2 p0 = __floats2half2_rn(lo.x * ns, lo.y * ns);
        __half2 p1 = __floats2half2_rn(hi.x * ns, hi.y * ns);
        uint2 st = make_uint2(*reinterpret_cast<unsigned*>(&p0),
                              *reinterpret_cast<unsigned*>(&p1));
        *reinterpret_cast<uint2*>(out + (size_t)row * OUT + tx * 4) = st;
    }
}

// ---------------- CSR SpMM (fp16 gather), fused finalize -----------------------------------
// warp per dst node, 4 halves (uint2) per lane for 128 features. fp32 accumulate.
template <bool SRCSCALE>
__global__ void spmm_csr128h_k(const __half* __restrict__ tmp,
                               const float* __restrict__ b,
                               float* __restrict__ h) {
    int w = (blockIdx.x * blockDim.x + threadIdx.x) >> 5;
    int lane = threadIdx.x & 31;
    if (w >= N_NODES) return;
    int beg = g_rowptr[w];
    int end = g_rowptr[w + 1];
    float4 acc = make_float4(0.f, 0.f, 0.f, 0.f);
    int i = beg;
    for (; i + 3 < end; i += 4) {
        int s0 = g_csr[i], s1 = g_csr[i + 1], s2 = g_csr[i + 2], s3 = g_csr[i + 3];
        uint2 u0 = *reinterpret_cast<const uint2*>(tmp + (size_t)s0 * 128 + lane * 4);
        uint2 u1 = *reinterpret_cast<const uint2*>(tmp + (size_t)s1 * 128 + lane * 4);
        uint2 u2 = *reinterpret_cast<const uint2*>(tmp + (size_t)s2 * 128 + lane * 4);
        uint2 u3 = *reinterpret_cast<const uint2*>(tmp + (size_t)s3 * 128 + lane * 4);
        float2 a0 = __half22float2(*reinterpret_cast<__half2*>(&u0.x));
        float2 b0_ = __half22float2(*reinterpret_cast<__half2*>(&u0.y));
        float2 a1 = __half22float2(*reinterpret_cast<__half2*>(&u1.x));
        float2 b1_ = __half22float2(*reinterpret_cast<__half2*>(&u1.y));
        float2 a2 = __half22float2(*reinterpret_cast<__half2*>(&u2.x));
        float2 b2_ = __half22float2(*reinterpret_cast<__half2*>(&u2.y));
        float2 a3 = __half22float2(*reinterpret_cast<__half2*>(&u3.x));
        float2 b3_ = __half22float2(*reinterpret_cast<__half2*>(&u3.y));
        if (SRCSCALE) {
            float n0 = __ldg(&g_nsrc[s0]), n1 = __ldg(&g_nsrc[s1]);
            float n2 = __ldg(&g_nsrc[s2]), n3 = __ldg(&g_nsrc[s3]);
            acc.x += a0.x * n0 + a1.x * n1 + a2.x * n2 + a3.x * n3;
            acc.y += a0.y * n0 + a1.y * n1 + a2.y * n2 + a3.y * n3;
            acc.z += b0_.x * n0 + b1_.x * n1 + b2_.x * n2 + b3_.x * n3;
            acc.w += b0_.y * n0 + b1_.y * n1 + b2_.y * n2 + b3_.y * n3;
        } else {
            acc.x += a0.x + a1.x + a2.x + a3.x;
            acc.y += a0.y + a1.y + a2.y + a3.y;
            acc.z += b0_.x + b1_.x + b2_.x + b3_.x;
            acc.w += b0_.y + b1_.y + b2_.y + b3_.y;
        }
    }
    for (; i < end; i++) {
        int s = g_csr[i];
        uint2 u = *reinterpret_cast<const uint2*>(tmp + (size_t)s * 128 + lane * 4);
        float2 a = __half22float2(*reinterpret_cast<__half2*>(&u.x));
        float2 c = __half22float2(*reinterpret_cast<__half2*>(&u.y));
        float ns = SRCSCALE ? __ldg(&g_nsrc[s]) : 1.0f;
        acc.x += a.x * ns; acc.y += a.y * ns; acc.z += c.x * ns; acc.w += c.y * ns;
    }
    float nd = g_ndst[w];
    float4 bb = *reinterpret_cast<const float4*>(b + lane * 4);
    float4 o = make_float4(acc.x * nd + bb.x, acc.y * nd + bb.y,
                           acc.z * nd + bb.z, acc.w * nd + bb.w);
    *reinterpret_cast<float4*>(h + (size_t)w * 128 + lane * 4) = o;
}

// 64 features fp16 gather, fused finalize + softmax. warp per dst node, half2 per lane.
__global__ void spmm_csr64h_softmax_k(const __half* __restrict__ tmp,
                                      const float* __restrict__ b,
                                      float* __restrict__ out) {
    int w = (blockIdx.x * blockDim.x + threadIdx.x) >> 5;
    int lane = threadIdx.x & 31;
    if (w >= N_NODES) return;
    int beg = g_rowptr[w];
    int end = g_rowptr[w + 1];
    float2 acc = make_float2(0.f, 0.f);
    int i = beg;
    for (; i + 3 < end; i += 4) {
        int s0 = g_csr[i], s1 = g_csr[i + 1], s2 = g_csr[i + 2], s3 = g_csr[i + 3];
        float2 v0 = __half22float2(*reinterpret_cast<const __half2*>(tmp + (size_t)s0 * 64 + lane * 2));
        float2 v1 = __half22float2(*reinterpret_cast<const __half2*>(tmp + (size_t)s1 * 64 + lane * 2));
        float2 v2 = __half22float2(*reinterpret_cast<const __half2*>(tmp + (size_t)s2 * 64 + lane * 2));
        float2 v3 = __half22float2(*reinterpret_cast<const __half2*>(tmp + (size_t)s3 * 64 + lane * 2));
        acc.x += v0.x + v1.x + v2.x + v3.x;
        acc.y += v0.y + v1.y + v2.y + v3.y;
    }
    for (; i < end; i++) {
        int s = g_csr[i];
        float2 v = __half22float2(*reinterpret_cast<const __half2*>(tmp + (size_t)s * 64 + lane * 2));
        acc.x += v.x; acc.y += v.y;
    }
    float nd = g_ndst[w];
    float2 bb = *reinterpret_cast<const float2*>(b + lane * 2);
    float a0 = acc.x * nd + bb.x;
    float a1 = acc.y * nd + bb.y;
    float m = fmaxf(a0, a1);
#pragma unroll
    for (int o = 16; o > 0; o >>= 1) m = fmaxf(m, __shfl_xor_sync(0xffffffffu, m, o));
    float e0 = __expf(a0 - m);
    float e1 = __expf(a1 - m);
    float s = e0 + e1;
#pragma unroll
    for (int o = 16; o > 0; o >>= 1) s += __shfl_xor_sync(0xffffffffu, s, o);
    float inv = 1.f / s;
    reinterpret_cast<float2*>(out + (size_t)w * 64)[lane] = make_float2(e0 * inv, e1 * inv);
}

// ---------------- launch ----------------

extern "C" void kernel_launch(void* const* d_in, const int* in_sizes, int n_in,
                              void* d_out, int out_size) {
    const float* x = (const float*)d_in[0];
    const int* src = (const int*)d_in[1];
    const int* dst = (const int*)d_in[2];
    const float* W0 = (const float*)d_in[3];
    const float* b0 = (const float*)d_in[4];
    const float* W1 = (const float*)d_in[5];
    const float* b1 = (const float*)d_in[6];
    const float* W2 = (const float*)d_in[7];
    const float* b2 = (const float*)d_in[8];
    float* out = (float*)d_out;

    __half* tmph;
    float* h;
    cudaGetSymbolAddress((void**)&tmph, g_tmph);
    cudaGetSymbolAddress((void**)&h, g_h);

    // one-time host objects (no device memory)
    static cudaStream_t s_side = nullptr;
    static cudaEvent_t s_fork = nullptr, s_join = nullptr;
    if (s_side == nullptr) {
        cudaStreamCreateWithFlags(&s_side, cudaStreamNonBlocking);
        cudaEventCreateWithFlags(&s_fork, cudaEventDisableTiming);
        cudaEventCreateWithFlags(&s_join, cudaEventDisableTiming);
    }

    const int TPB = 256;
    const int nodeBlocks = (N_NODES + TPB - 1) / TPB;
    const int edgeBlocks = (E_EDGES + TPB - 1) / TPB;
    const int nodeWarpBlocks = (int)(((size_t)N_NODES * 32 + TPB - 1) / TPB);

    // fork: layer-0 GEMM (unscaled — independent of degree/norms) on side stream
    cudaEventRecord(s_fork, 0);
    cudaStreamWaitEvent(s_side, s_fork, 0);
    gemm_h_k<NFEAT, NHID, false><<<N_NODES / 32, 128, 0, s_side>>>(x, W0, tmph);
    cudaEventRecord(s_join, s_side);

    // CSR build chain on main stream (concurrent with GEMM0)
    zero_deg_k<<<nodeBlocks, TPB>>>();
    degree_k<<<edgeBlocks, TPB>>>(src, dst);
    norms_k<<<nodeBlocks, TPB>>>();
    blocksum_k<<<SCAN_NB, 256>>>();
    scanblocks_k<<<1, 128>>>();
    localscan_k<<<SCAN_NB, 256>>>();
    scatter_k<<<edgeBlocks, TPB>>>(src, dst);

    // join
    cudaStreamWaitEvent(0, s_join, 0);

    // ---- Layer 0: SpMM applies n_src per gathered row ----
    spmm_csr128h_k<true><<<nodeWarpBlocks, TPB>>>(tmph, b0, h);

    // ---- Layer 1: 128 -> 128 ----
    gemm_h_k<NHID, NHID, true><<<N_NODES / 32, 128>>>(h, W1, tmph);
    spmm_csr128h_k<false><<<nodeWarpBlocks, TPB>>>(tmph, b1, h);

    // ---- Layer 2: 128 -> 64, + softmax ----
    gemm_h_k<NHID, NCLASS, true><<<N_NODES / 32, 128>>>(h, W2, tmph);
    spmm_csr64h_softmax_k<<<nodeWarpBlocks, TPB>>>(tmph, b2, out);
}